// round 14
// baseline (speedup 1.0000x reference)
#include <cuda_runtime.h>
#include <math.h>

#define NNODES 50000
#define DIM 256

// Scratch (allocation-free rule): aggregation buffer + two hidden layers.
__device__ float g_agg[(size_t)NNODES * DIM];
__device__ float g_h1 [(size_t)NNODES * DIM];
__device__ float g_h2 [(size_t)NNODES * DIM];
__device__ int   g_idx_stride;   // 1 = indices are int32, 2 = indices are int64 (read low word)

// ---------------------------------------------------------------------------
// Detect edge_index dtype. For int64 little-endian with values < 2^31, every
// odd 32-bit word of the first 32 elements is zero. For int32, those words are
// random node ids (all-zero probability ~ (1/50000)^32 ~ 0).
__global__ void k_detect(const int* __restrict__ ei) {
    int s = 2;
    #pragma unroll
    for (int i = 1; i < 64; i += 2)
        if (ei[i] != 0) { s = 1; break; }
    g_idx_stride = s;
}

// ---------------------------------------------------------------------------
// Zero the aggregation buffer (float4 stores).
__global__ void k_zero(float* __restrict__ p, int n4) {
    int i = blockIdx.x * blockDim.x + threadIdx.x;
    if (i < n4) reinterpret_cast<float4*>(p)[i] = make_float4(0.f, 0.f, 0.f, 0.f);
}

// ---------------------------------------------------------------------------
// Scatter-add: agg[dst] += h[src], 32 threads per edge, 8 floats per thread.
// Vectorized global reductions (red.global.add.v4.f32, sm_90+) quarter the
// L2 atomic-op count vs scalar atomicAdd.
__global__ void k_scatter(const float* __restrict__ h,
                          const int* __restrict__ ei,   // words; stride from g_idx_stride
                          float* __restrict__ agg, int E) {
    int t = blockIdx.x * blockDim.x + threadIdx.x;
    int e = t >> 5;                 // 32 threads / edge
    if (e >= E) return;
    const int stride = g_idx_stride;
    int c = (t & 31) * 8;           // 8 consecutive features per thread
    int s = ei[(size_t)e * stride];
    int d = ei[((size_t)E + e) * stride];
    const float4* hp = reinterpret_cast<const float4*>(h + (size_t)s * DIM + c);
    float4 v0 = hp[0];
    float4 v1 = hp[1];
    float* op = agg + (size_t)d * DIM + c;
    asm volatile("red.global.add.v4.f32 [%0], {%1,%2,%3,%4};"
                 :: "l"(op),     "f"(v0.x), "f"(v0.y), "f"(v0.z), "f"(v0.w) : "memory");
    asm volatile("red.global.add.v4.f32 [%0], {%1,%2,%3,%4};"
                 :: "l"(op + 4), "f"(v1.x), "f"(v1.y), "f"(v1.z), "f"(v1.w) : "memory");
}

// ---------------------------------------------------------------------------
// Fused dual GEMM + bias + ELU:
//   out[M,256] = elu( A1[M,256] @ W1[256,256] + A2[M,256] @ W2[256,256] + b )
// Tiling: 128x128 block tile, K-tile 8, 256 threads, 8x8 per thread.
#define BM 128
#define BN 128
#define BK 8

__device__ __forceinline__ float elu1(float x) {
    return x > 0.f ? x : expm1f(x);
}

__global__ __launch_bounds__(256)
void k_gemm2_bias_elu(const float* __restrict__ A1, const float* __restrict__ W1,
                      const float* __restrict__ A2, const float* __restrict__ W2,
                      const float* __restrict__ bias, float* __restrict__ out, int M) {
    __shared__ float As[BK][BM + 4];   // +4 pad: conflict-free transposed stores
    __shared__ float Bs[BK][BN];

    const int t    = threadIdx.x;
    const int row0 = blockIdx.x * BM;
    const int col0 = blockIdx.y * BN;

    // A-tile loader: thread -> (row, 4-wide k chunk)
    const int arow = t >> 1;           // 0..127
    const int acol = (t & 1) * 4;      // 0 or 4
    // B-tile loader: thread -> (k row, 4-wide col chunk)
    const int brow = t >> 5;           // 0..7
    const int bcol = (t & 31) * 4;     // 0..124

    const int tr = (t >> 4) * 8;       // thread's row offset in tile (0..120)
    const int tc = (t & 15) * 8;       // thread's col offset in tile (0..120)

    float acc[8][8];
    #pragma unroll
    for (int i = 0; i < 8; ++i)
        #pragma unroll
        for (int j = 0; j < 8; ++j) acc[i][j] = 0.f;

    #pragma unroll
    for (int pass = 0; pass < 2; ++pass) {
        const float* A = pass ? A2 : A1;
        const float* W = pass ? W2 : W1;

        for (int k0 = 0; k0 < 256; k0 += BK) {
            // ---- load A tile (transposed into smem) ----
            float4 av = make_float4(0.f, 0.f, 0.f, 0.f);
            int gr = row0 + arow;
            if (gr < M)
                av = *reinterpret_cast<const float4*>(A + (size_t)gr * 256 + k0 + acol);
            As[acol + 0][arow] = av.x;
            As[acol + 1][arow] = av.y;
            As[acol + 2][arow] = av.z;
            As[acol + 3][arow] = av.w;
            // ---- load B tile ----
            float4 bv = *reinterpret_cast<const float4*>(
                W + (size_t)(k0 + brow) * 256 + col0 + bcol);
            *reinterpret_cast<float4*>(&Bs[brow][bcol]) = bv;
            __syncthreads();

            #pragma unroll
            for (int k = 0; k < BK; ++k) {
                float4 a0 = *reinterpret_cast<const float4*>(&As[k][tr]);
                float4 a1 = *reinterpret_cast<const float4*>(&As[k][tr + 4]);
                float4 b0 = *reinterpret_cast<const float4*>(&Bs[k][tc]);
                float4 b1 = *reinterpret_cast<const float4*>(&Bs[k][tc + 4]);
                float a[8] = {a0.x, a0.y, a0.z, a0.w, a1.x, a1.y, a1.z, a1.w};
                float b[8] = {b0.x, b0.y, b0.z, b0.w, b1.x, b1.y, b1.z, b1.w};
                #pragma unroll
                for (int i = 0; i < 8; ++i)
                    #pragma unroll
                    for (int j = 0; j < 8; ++j)
                        acc[i][j] = fmaf(a[i], b[j], acc[i][j]);
            }
            __syncthreads();
        }
    }

    // ---- epilogue: + bias, ELU, store ----
    const int cbase = col0 + tc;
    float bb[8];
    #pragma unroll
    for (int j = 0; j < 8; ++j) bb[j] = bias[cbase + j];

    #pragma unroll
    for (int i = 0; i < 8; ++i) {
        int r = row0 + tr + i;
        if (r < M) {
            float4 v0, v1;
            v0.x = elu1(acc[i][0] + bb[0]);
            v0.y = elu1(acc[i][1] + bb[1]);
            v0.z = elu1(acc[i][2] + bb[2]);
            v0.w = elu1(acc[i][3] + bb[3]);
            v1.x = elu1(acc[i][4] + bb[4]);
            v1.y = elu1(acc[i][5] + bb[5]);
            v1.z = elu1(acc[i][6] + bb[6]);
            v1.w = elu1(acc[i][7] + bb[7]);
            float* o = out + (size_t)r * 256 + cbase;
            *reinterpret_cast<float4*>(o)     = v0;
            *reinterpret_cast<float4*>(o + 4) = v1;
        }
    }
}

// ---------------------------------------------------------------------------
extern "C" void kernel_launch(void* const* d_in, const int* in_sizes, int n_in,
                              void* d_out, int out_size) {
    const float* x   = (const float*)d_in[0];
    const int*   ei  = (const int*)d_in[1];    // int32 or int64 words; detected on device
    const float* W1r = (const float*)d_in[2];
    const float* b1  = (const float*)d_in[3];
    const float* W1o = (const float*)d_in[4];
    const float* W2r = (const float*)d_in[5];
    const float* b2  = (const float*)d_in[6];
    const float* W2o = (const float*)d_in[7];
    const float* W3r = (const float*)d_in[8];
    const float* b3  = (const float*)d_in[9];
    const float* W3o = (const float*)d_in[10];
    float* out = (float*)d_out;

    const int M = in_sizes[0] / DIM;       // 50000
    const int E = in_sizes[1] / 2;         // 800000 (element count is 2*E for either dtype)

    float *agg, *h1, *h2;
    cudaGetSymbolAddress((void**)&agg, g_agg);
    cudaGetSymbolAddress((void**)&h1,  g_h1);
    cudaGetSymbolAddress((void**)&h2,  g_h2);

    const int n4        = (M * DIM) / 4;
    const int zeroGrid  = (n4 + 255) / 256;
    const int scatGrid  = ((E * 32) + 255) / 256;
    dim3 gemmGrid((M + BM - 1) / BM, 256 / BN);

    k_detect<<<1, 1>>>(ei);

    // Layer 1: x -> h1
    k_zero<<<zeroGrid, 256>>>(agg, n4);
    k_scatter<<<scatGrid, 256>>>(x, ei, agg, E);
    k_gemm2_bias_elu<<<gemmGrid, 256>>>(agg, W1r, x, W1o, b1, h1, M);

    // Layer 2: h1 -> h2
    k_zero<<<zeroGrid, 256>>>(agg, n4);
    k_scatter<<<scatGrid, 256>>>(h1, ei, agg, E);
    k_gemm2_bias_elu<<<gemmGrid, 256>>>(agg, W2r, h1, W2o, b2, h2, M);

    // Layer 3: h2 -> out
    k_zero<<<zeroGrid, 256>>>(agg, n4);
    k_scatter<<<scatGrid, 256>>>(h2, ei, agg, E);
    k_gemm2_bias_elu<<<gemmGrid, 256>>>(agg, W3r, h2, W3o, b3, out, M);
}

// round 15
// speedup vs baseline: 1.0031x; 1.0031x over previous
#include <cuda_runtime.h>
#include <math.h>

#define NNODES 50000
#define DIM 256

// Scratch (allocation-free rule): aggregation buffer + two hidden layers.
__device__ float g_agg[(size_t)NNODES * DIM];
__device__ float g_h1 [(size_t)NNODES * DIM];
__device__ float g_h2 [(size_t)NNODES * DIM];
__device__ int   g_idx_stride;   // 1 = indices are int32, 2 = indices are int64 (read low word)

// ---------------------------------------------------------------------------
// Detect edge_index dtype. For int64 little-endian with values < 2^31, every
// odd 32-bit word of the first 32 elements is zero. For int32, those words are
// random node ids (all-zero probability ~ (1/50000)^32 ~ 0).
__global__ void k_detect(const int* __restrict__ ei) {
    int s = 2;
    #pragma unroll
    for (int i = 1; i < 64; i += 2)
        if (ei[i] != 0) { s = 1; break; }
    g_idx_stride = s;
}

// ---------------------------------------------------------------------------
// Zero the aggregation buffer (float4 stores).
__global__ void k_zero(float* __restrict__ p, int n4) {
    int i = blockIdx.x * blockDim.x + threadIdx.x;
    if (i < n4) reinterpret_cast<float4*>(p)[i] = make_float4(0.f, 0.f, 0.f, 0.f);
}

// ---------------------------------------------------------------------------
// Scatter-add: agg[dst] += h[src], 32 threads per edge, 8 floats per thread.
// Vectorized global reductions (red.global.add.v4.f32, sm_90+) quarter the
// L2 atomic-op count vs scalar atomicAdd.
__global__ void k_scatter(const float* __restrict__ h,
                          const int* __restrict__ ei,   // words; stride from g_idx_stride
                          float* __restrict__ agg, int E) {
    int t = blockIdx.x * blockDim.x + threadIdx.x;
    int e = t >> 5;                 // 32 threads / edge
    if (e >= E) return;
    const int stride = g_idx_stride;
    int c = (t & 31) * 8;           // 8 consecutive features per thread
    int s = ei[(size_t)e * stride];
    int d = ei[((size_t)E + e) * stride];
    const float4* hp = reinterpret_cast<const float4*>(h + (size_t)s * DIM + c);
    float4 v0 = hp[0];
    float4 v1 = hp[1];
    float* op = agg + (size_t)d * DIM + c;
    asm volatile("red.global.add.v4.f32 [%0], {%1,%2,%3,%4};"
                 :: "l"(op),     "f"(v0.x), "f"(v0.y), "f"(v0.z), "f"(v0.w) : "memory");
    asm volatile("red.global.add.v4.f32 [%0], {%1,%2,%3,%4};"
                 :: "l"(op + 4), "f"(v1.x), "f"(v1.y), "f"(v1.z), "f"(v1.w) : "memory");
}

// ---------------------------------------------------------------------------
// Fused dual GEMM + bias + ELU:
//   out[M,256] = elu( A1[M,256] @ W1[256,256] + A2[M,256] @ W2[256,256] + b )
// Tiling: 128x128 block tile, K-tile 8, 256 threads, 8x8 per thread.
#define BM 128
#define BN 128
#define BK 8

__device__ __forceinline__ float elu1(float x) {
    return x > 0.f ? x : expm1f(x);
}

__global__ __launch_bounds__(256)
void k_gemm2_bias_elu(const float* __restrict__ A1, const float* __restrict__ W1,
                      const float* __restrict__ A2, const float* __restrict__ W2,
                      const float* __restrict__ bias, float* __restrict__ out, int M) {
    __shared__ float As[BK][BM + 4];   // +4 pad: conflict-free transposed stores
    __shared__ float Bs[BK][BN];

    const int t    = threadIdx.x;
    const int row0 = blockIdx.x * BM;
    const int col0 = blockIdx.y * BN;

    // A-tile loader: thread -> (row, 4-wide k chunk)
    const int arow = t >> 1;           // 0..127
    const int acol = (t & 1) * 4;      // 0 or 4
    // B-tile loader: thread -> (k row, 4-wide col chunk)
    const int brow = t >> 5;           // 0..7
    const int bcol = (t & 31) * 4;     // 0..124

    const int tr = (t >> 4) * 8;       // thread's row offset in tile (0..120)
    const int tc = (t & 15) * 8;       // thread's col offset in tile (0..120)

    float acc[8][8];
    #pragma unroll
    for (int i = 0; i < 8; ++i)
        #pragma unroll
        for (int j = 0; j < 8; ++j) acc[i][j] = 0.f;

    #pragma unroll
    for (int pass = 0; pass < 2; ++pass) {
        const float* A = pass ? A2 : A1;
        const float* W = pass ? W2 : W1;

        for (int k0 = 0; k0 < 256; k0 += BK) {
            // ---- load A tile (transposed into smem) ----
            float4 av = make_float4(0.f, 0.f, 0.f, 0.f);
            int gr = row0 + arow;
            if (gr < M)
                av = *reinterpret_cast<const float4*>(A + (size_t)gr * 256 + k0 + acol);
            As[acol + 0][arow] = av.x;
            As[acol + 1][arow] = av.y;
            As[acol + 2][arow] = av.z;
            As[acol + 3][arow] = av.w;
            // ---- load B tile ----
            float4 bv = *reinterpret_cast<const float4*>(
                W + (size_t)(k0 + brow) * 256 + col0 + bcol);
            *reinterpret_cast<float4*>(&Bs[brow][bcol]) = bv;
            __syncthreads();

            #pragma unroll
            for (int k = 0; k < BK; ++k) {
                float4 a0 = *reinterpret_cast<const float4*>(&As[k][tr]);
                float4 a1 = *reinterpret_cast<const float4*>(&As[k][tr + 4]);
                float4 b0 = *reinterpret_cast<const float4*>(&Bs[k][tc]);
                float4 b1 = *reinterpret_cast<const float4*>(&Bs[k][tc + 4]);
                float a[8] = {a0.x, a0.y, a0.z, a0.w, a1.x, a1.y, a1.z, a1.w};
                float b[8] = {b0.x, b0.y, b0.z, b0.w, b1.x, b1.y, b1.z, b1.w};
                #pragma unroll
                for (int i = 0; i < 8; ++i)
                    #pragma unroll
                    for (int j = 0; j < 8; ++j)
                        acc[i][j] = fmaf(a[i], b[j], acc[i][j]);
            }
            __syncthreads();
        }
    }

    // ---- epilogue: + bias, ELU, store ----
    const int cbase = col0 + tc;
    float bb[8];
    #pragma unroll
    for (int j = 0; j < 8; ++j) bb[j] = bias[cbase + j];

    #pragma unroll
    for (int i = 0; i < 8; ++i) {
        int r = row0 + tr + i;
        if (r < M) {
            float4 v0, v1;
            v0.x = elu1(acc[i][0] + bb[0]);
            v0.y = elu1(acc[i][1] + bb[1]);
            v0.z = elu1(acc[i][2] + bb[2]);
            v0.w = elu1(acc[i][3] + bb[3]);
            v1.x = elu1(acc[i][4] + bb[4]);
            v1.y = elu1(acc[i][5] + bb[5]);
            v1.z = elu1(acc[i][6] + bb[6]);
            v1.w = elu1(acc[i][7] + bb[7]);
            float* o = out + (size_t)r * 256 + cbase;
            *reinterpret_cast<float4*>(o)     = v0;
            *reinterpret_cast<float4*>(o + 4) = v1;
        }
    }
}

// ---------------------------------------------------------------------------
extern "C" void kernel_launch(void* const* d_in, const int* in_sizes, int n_in,
                              void* d_out, int out_size) {
    const float* x   = (const float*)d_in[0];
    const int*   ei  = (const int*)d_in[1];    // int32 or int64 words; detected on device
    const float* W1r = (const float*)d_in[2];
    const float* b1  = (const float*)d_in[3];
    const float* W1o = (const float*)d_in[4];
    const float* W2r = (const float*)d_in[5];
    const float* b2  = (const float*)d_in[6];
    const float* W2o = (const float*)d_in[7];
    const float* W3r = (const float*)d_in[8];
    const float* b3  = (const float*)d_in[9];
    const float* W3o = (const float*)d_in[10];
    float* out = (float*)d_out;

    const int M = in_sizes[0] / DIM;       // 50000
    const int E = in_sizes[1] / 2;         // 800000 (element count is 2*E for either dtype)

    float *agg, *h1, *h2;
    cudaGetSymbolAddress((void**)&agg, g_agg);
    cudaGetSymbolAddress((void**)&h1,  g_h1);
    cudaGetSymbolAddress((void**)&h2,  g_h2);

    const int n4        = (M * DIM) / 4;
    const int zeroGrid  = (n4 + 255) / 256;
    const int scatGrid  = ((E * 32) + 255) / 256;
    dim3 gemmGrid((M + BM - 1) / BM, 256 / BN);

    k_detect<<<1, 1>>>(ei);

    // Layer 1: x -> h1
    k_zero<<<zeroGrid, 256>>>(agg, n4);
    k_scatter<<<scatGrid, 256>>>(x, ei, agg, E);
    k_gemm2_bias_elu<<<gemmGrid, 256>>>(agg, W1r, x, W1o, b1, h1, M);

    // Layer 2: h1 -> h2
    k_zero<<<zeroGrid, 256>>>(agg, n4);
    k_scatter<<<scatGrid, 256>>>(h1, ei, agg, E);
    k_gemm2_bias_elu<<<gemmGrid, 256>>>(agg, W2r, h1, W2o, b2, h2, M);

    // Layer 3: h2 -> out
    k_zero<<<zeroGrid, 256>>>(agg, n4);
    k_scatter<<<scatGrid, 256>>>(h2, ei, agg, E);
    k_gemm2_bias_elu<<<gemmGrid, 256>>>(agg, W3r, h2, W3o, b3, out, M);
}

// round 16
// speedup vs baseline: 1.0032x; 1.0001x over previous
#include <cuda_runtime.h>
#include <math.h>

#define NNODES 50000
#define DIM 256

// Scratch (allocation-free rule): aggregation buffer + two hidden layers.
__device__ float g_agg[(size_t)NNODES * DIM];
__device__ float g_h1 [(size_t)NNODES * DIM];
__device__ float g_h2 [(size_t)NNODES * DIM];
__device__ int   g_idx_stride;   // 1 = indices are int32, 2 = indices are int64 (read low word)

// ---------------------------------------------------------------------------
// Detect edge_index dtype. For int64 little-endian with values < 2^31, every
// odd 32-bit word of the first 32 elements is zero. For int32, those words are
// random node ids (all-zero probability ~ (1/50000)^32 ~ 0).
__global__ void k_detect(const int* __restrict__ ei) {
    int s = 2;
    #pragma unroll
    for (int i = 1; i < 64; i += 2)
        if (ei[i] != 0) { s = 1; break; }
    g_idx_stride = s;
}

// ---------------------------------------------------------------------------
// Zero the aggregation buffer (float4 stores).
__global__ void k_zero(float* __restrict__ p, int n4) {
    int i = blockIdx.x * blockDim.x + threadIdx.x;
    if (i < n4) reinterpret_cast<float4*>(p)[i] = make_float4(0.f, 0.f, 0.f, 0.f);
}

// ---------------------------------------------------------------------------
// Scatter-add: agg[dst] += h[src], 32 threads per edge, 8 floats per thread.
// Vectorized global reductions (red.global.add.v4.f32, sm_90+) quarter the
// L2 atomic-op count vs scalar atomicAdd.
__global__ void k_scatter(const float* __restrict__ h,
                          const int* __restrict__ ei,   // words; stride from g_idx_stride
                          float* __restrict__ agg, int E) {
    int t = blockIdx.x * blockDim.x + threadIdx.x;
    int e = t >> 5;                 // 32 threads / edge
    if (e >= E) return;
    const int stride = g_idx_stride;
    int c = (t & 31) * 8;           // 8 consecutive features per thread
    int s = ei[(size_t)e * stride];
    int d = ei[((size_t)E + e) * stride];
    const float4* hp = reinterpret_cast<const float4*>(h + (size_t)s * DIM + c);
    float4 v0 = hp[0];
    float4 v1 = hp[1];
    float* op = agg + (size_t)d * DIM + c;
    asm volatile("red.global.add.v4.f32 [%0], {%1,%2,%3,%4};"
                 :: "l"(op),     "f"(v0.x), "f"(v0.y), "f"(v0.z), "f"(v0.w) : "memory");
    asm volatile("red.global.add.v4.f32 [%0], {%1,%2,%3,%4};"
                 :: "l"(op + 4), "f"(v1.x), "f"(v1.y), "f"(v1.z), "f"(v1.w) : "memory");
}

// ---------------------------------------------------------------------------
// Fused dual GEMM + bias + ELU:
//   out[M,256] = elu( A1[M,256] @ W1[256,256] + A2[M,256] @ W2[256,256] + b )
// Tiling: 128x128 block tile, K-tile 8, 256 threads, 8x8 per thread.
#define BM 128
#define BN 128
#define BK 8

__device__ __forceinline__ float elu1(float x) {
    return x > 0.f ? x : expm1f(x);
}

__global__ __launch_bounds__(256)
void k_gemm2_bias_elu(const float* __restrict__ A1, const float* __restrict__ W1,
                      const float* __restrict__ A2, const float* __restrict__ W2,
                      const float* __restrict__ bias, float* __restrict__ out, int M) {
    __shared__ float As[BK][BM + 4];   // +4 pad: conflict-free transposed stores
    __shared__ float Bs[BK][BN];

    const int t    = threadIdx.x;
    const int row0 = blockIdx.x * BM;
    const int col0 = blockIdx.y * BN;

    // A-tile loader: thread -> (row, 4-wide k chunk)
    const int arow = t >> 1;           // 0..127
    const int acol = (t & 1) * 4;      // 0 or 4
    // B-tile loader: thread -> (k row, 4-wide col chunk)
    const int brow = t >> 5;           // 0..7
    const int bcol = (t & 31) * 4;     // 0..124

    const int tr = (t >> 4) * 8;       // thread's row offset in tile (0..120)
    const int tc = (t & 15) * 8;       // thread's col offset in tile (0..120)

    float acc[8][8];
    #pragma unroll
    for (int i = 0; i < 8; ++i)
        #pragma unroll
        for (int j = 0; j < 8; ++j) acc[i][j] = 0.f;

    #pragma unroll
    for (int pass = 0; pass < 2; ++pass) {
        const float* A = pass ? A2 : A1;
        const float* W = pass ? W2 : W1;

        for (int k0 = 0; k0 < 256; k0 += BK) {
            // ---- load A tile (transposed into smem) ----
            float4 av = make_float4(0.f, 0.f, 0.f, 0.f);
            int gr = row0 + arow;
            if (gr < M)
                av = *reinterpret_cast<const float4*>(A + (size_t)gr * 256 + k0 + acol);
            As[acol + 0][arow] = av.x;
            As[acol + 1][arow] = av.y;
            As[acol + 2][arow] = av.z;
            As[acol + 3][arow] = av.w;
            // ---- load B tile ----
            float4 bv = *reinterpret_cast<const float4*>(
                W + (size_t)(k0 + brow) * 256 + col0 + bcol);
            *reinterpret_cast<float4*>(&Bs[brow][bcol]) = bv;
            __syncthreads();

            #pragma unroll
            for (int k = 0; k < BK; ++k) {
                float4 a0 = *reinterpret_cast<const float4*>(&As[k][tr]);
                float4 a1 = *reinterpret_cast<const float4*>(&As[k][tr + 4]);
                float4 b0 = *reinterpret_cast<const float4*>(&Bs[k][tc]);
                float4 b1 = *reinterpret_cast<const float4*>(&Bs[k][tc + 4]);
                float a[8] = {a0.x, a0.y, a0.z, a0.w, a1.x, a1.y, a1.z, a1.w};
                float b[8] = {b0.x, b0.y, b0.z, b0.w, b1.x, b1.y, b1.z, b1.w};
                #pragma unroll
                for (int i = 0; i < 8; ++i)
                    #pragma unroll
                    for (int j = 0; j < 8; ++j)
                        acc[i][j] = fmaf(a[i], b[j], acc[i][j]);
            }
            __syncthreads();
        }
    }

    // ---- epilogue: + bias, ELU, store ----
    const int cbase = col0 + tc;
    float bb[8];
    #pragma unroll
    for (int j = 0; j < 8; ++j) bb[j] = bias[cbase + j];

    #pragma unroll
    for (int i = 0; i < 8; ++i) {
        int r = row0 + tr + i;
        if (r < M) {
            float4 v0, v1;
            v0.x = elu1(acc[i][0] + bb[0]);
            v0.y = elu1(acc[i][1] + bb[1]);
            v0.z = elu1(acc[i][2] + bb[2]);
            v0.w = elu1(acc[i][3] + bb[3]);
            v1.x = elu1(acc[i][4] + bb[4]);
            v1.y = elu1(acc[i][5] + bb[5]);
            v1.z = elu1(acc[i][6] + bb[6]);
            v1.w = elu1(acc[i][7] + bb[7]);
            float* o = out + (size_t)r * 256 + cbase;
            *reinterpret_cast<float4*>(o)     = v0;
            *reinterpret_cast<float4*>(o + 4) = v1;
        }
    }
}

// ---------------------------------------------------------------------------
extern "C" void kernel_launch(void* const* d_in, const int* in_sizes, int n_in,
                              void* d_out, int out_size) {
    const float* x   = (const float*)d_in[0];
    const int*   ei  = (const int*)d_in[1];    // int32 or int64 words; detected on device
    const float* W1r = (const float*)d_in[2];
    const float* b1  = (const float*)d_in[3];
    const float* W1o = (const float*)d_in[4];
    const float* W2r = (const float*)d_in[5];
    const float* b2  = (const float*)d_in[6];
    const float* W2o = (const float*)d_in[7];
    const float* W3r = (const float*)d_in[8];
    const float* b3  = (const float*)d_in[9];
    const float* W3o = (const float*)d_in[10];
    float* out = (float*)d_out;

    const int M = in_sizes[0] / DIM;       // 50000
    const int E = in_sizes[1] / 2;         // 800000 (element count is 2*E for either dtype)

    float *agg, *h1, *h2;
    cudaGetSymbolAddress((void**)&agg, g_agg);
    cudaGetSymbolAddress((void**)&h1,  g_h1);
    cudaGetSymbolAddress((void**)&h2,  g_h2);

    const int n4        = (M * DIM) / 4;
    const int zeroGrid  = (n4 + 255) / 256;
    const int scatGrid  = ((E * 32) + 255) / 256;
    dim3 gemmGrid((M + BM - 1) / BM, 256 / BN);

    k_detect<<<1, 1>>>(ei);

    // Layer 1: x -> h1
    k_zero<<<zeroGrid, 256>>>(agg, n4);
    k_scatter<<<scatGrid, 256>>>(x, ei, agg, E);
    k_gemm2_bias_elu<<<gemmGrid, 256>>>(agg, W1r, x, W1o, b1, h1, M);

    // Layer 2: h1 -> h2
    k_zero<<<zeroGrid, 256>>>(agg, n4);
    k_scatter<<<scatGrid, 256>>>(h1, ei, agg, E);
    k_gemm2_bias_elu<<<gemmGrid, 256>>>(agg, W2r, h1, W2o, b2, h2, M);

    // Layer 3: h2 -> out
    k_zero<<<zeroGrid, 256>>>(agg, n4);
    k_scatter<<<scatGrid, 256>>>(h2, ei, agg, E);
    k_gemm2_bias_elu<<<gemmGrid, 256>>>(agg, W3r, h2, W3o, b3, out, M);
}